// round 2
// baseline (speedup 1.0000x reference)
#include <cuda_runtime.h>

// Grouped mean over skeleton nodes:
//   in  : [32, 512, 21, 256] f32   (bt = 16384 rows of 21*256)
//   out : [32, 512, 10, 256] f32
// NODE_MAP = [[1,2],[3,4],[5,6],[7,8],[0,9],[10,11,12],[13,14],[15,16],[17,18],[19,20]]

__constant__ int   c_n0[10]    = {1, 3, 5, 7, 0, 10, 13, 15, 17, 19};
__constant__ int   c_n1[10]    = {2, 4, 6, 8, 9, 11, 14, 16, 18, 20};
__constant__ int   c_n2[10]    = {-1, -1, -1, -1, -1, 12, -1, -1, -1, -1};
__constant__ float c_scale[10] = {0.5f, 0.5f, 0.5f, 0.5f, 0.5f,
                                  1.0f / 3.0f, 0.5f, 0.5f, 0.5f, 0.5f};

static constexpr int C4      = 64;        // 256 f32 / 4 per node row
static constexpr int IN_ROW4 = 21 * C4;   // 1344 float4 per bt row (input)

__device__ __forceinline__ float4 ld_cs4(const float4* p) {
    float4 v;
    asm volatile("ld.global.cs.v4.f32 {%0,%1,%2,%3}, [%4];"
                 : "=f"(v.x), "=f"(v.y), "=f"(v.z), "=f"(v.w) : "l"(p));
    return v;
}
__device__ __forceinline__ void st_cs4(float4* p, float4 v) {
    asm volatile("st.global.cs.v4.f32 [%0], {%1,%2,%3,%4};"
                 :: "l"(p), "f"(v.x), "f"(v.y), "f"(v.z), "f"(v.w) : "memory");
}

__device__ __forceinline__ float4 group_mean(const float4* __restrict__ in,
                                             int idx)
{
    int c4  = idx & (C4 - 1);
    int tmp = idx >> 6;              // bt*10 + m
    int m   = tmp % 10;
    int bt  = tmp / 10;

    const float4* row = in + (long long)bt * IN_ROW4;

    float4 a = ld_cs4(row + c_n0[m] * C4 + c4);
    float4 b = ld_cs4(row + c_n1[m] * C4 + c4);

    float sx = a.x + b.x;
    float sy = a.y + b.y;
    float sz = a.z + b.z;
    float sw = a.w + b.w;

    int n2 = c_n2[m];
    if (n2 >= 0) {
        float4 c = ld_cs4(row + n2 * C4 + c4);
        sx += c.x; sy += c.y; sz += c.z; sw += c.w;
    }

    float s = c_scale[m];
    return make_float4(sx * s, sy * s, sz * s, sw * s);
}

__global__ __launch_bounds__(256)
void s_down_sampling_kernel(const float4* __restrict__ in,
                            float4* __restrict__ out,
                            int total4)
{
    int stride = blockDim.x * gridDim.x;
    int i0 = blockIdx.x * blockDim.x + threadIdx.x;
    int i1 = i0 + stride;

    // Two independent outputs per thread: doubles outstanding loads (MLP)
    // before either store's dependency stalls the warp.
    if (i1 < total4) {
        float4 r0 = group_mean(in, i0);
        float4 r1 = group_mean(in, i1);
        st_cs4(out + i0, r0);
        st_cs4(out + i1, r1);
    } else if (i0 < total4) {
        float4 r0 = group_mean(in, i0);
        st_cs4(out + i0, r0);
    }
}

extern "C" void kernel_launch(void* const* d_in, const int* in_sizes, int n_in,
                              void* d_out, int out_size)
{
    const float4* in  = (const float4*)d_in[0];
    float4*       out = (float4*)d_out;

    int total4  = out_size / 4;                    // 10,485,760 / 4 = 2,621,440? (out_size elems/4)
    int threads = 256;
    int per_blk = threads * 2;                     // unroll 2
    int blocks  = (total4 + per_blk - 1) / per_blk;
    s_down_sampling_kernel<<<blocks, threads>>>(in, out, total4);
}

// round 3
// speedup vs baseline: 1.0045x; 1.0045x over previous
#include <cuda_runtime.h>

// Grouped mean over skeleton nodes:
//   in  : [32, 512, 21, 256] f32   (bt = 16384 rows of 21*256)
//   out : [32, 512, 10, 256] f32
// NODE_MAP = [[1,2],[3,4],[5,6],[7,8],[0,9],[10,11,12],[13,14],[15,16],[17,18],[19,20]]

__constant__ int   c_n0[10]    = {1, 3, 5, 7, 0, 10, 13, 15, 17, 19};
__constant__ int   c_n1[10]    = {2, 4, 6, 8, 9, 11, 14, 16, 18, 20};
__constant__ int   c_n2[10]    = {-1, -1, -1, -1, -1, 12, -1, -1, -1, -1};
__constant__ float c_scale[10] = {0.5f, 0.5f, 0.5f, 0.5f, 0.5f,
                                  1.0f / 3.0f, 0.5f, 0.5f, 0.5f, 0.5f};

static constexpr int C4      = 64;        // 256 f32 / 4 per node row
static constexpr int IN_ROW4 = 21 * C4;   // 1344 float4 per bt row (input)
static constexpr int UNROLL  = 4;

__device__ __forceinline__ float4 ld_cs4(const float4* p) {
    float4 v;
    asm volatile("ld.global.cs.v4.f32 {%0,%1,%2,%3}, [%4];"
                 : "=f"(v.x), "=f"(v.y), "=f"(v.z), "=f"(v.w) : "l"(p));
    return v;
}
__device__ __forceinline__ void st_cs4(float4* p, float4 v) {
    asm volatile("st.global.cs.v4.f32 [%0], {%1,%2,%3,%4};"
                 :: "l"(p), "f"(v.x), "f"(v.y), "f"(v.z), "f"(v.w) : "memory");
}

__global__ __launch_bounds__(256)
void s_down_sampling_kernel(const float4* __restrict__ in,
                            float4* __restrict__ out,
                            int total4)
{
    int stride = blockDim.x * gridDim.x;
    int base = blockIdx.x * blockDim.x + threadIdx.x;

    int   idx[UNROLL];
    const float4* pa[UNROLL];
    const float4* pb[UNROLL];
    const float4* pc[UNROLL];
    float sc[UNROLL];

    // Address computation for all lanes first.
    #pragma unroll
    for (int u = 0; u < UNROLL; u++) {
        int i = base + u * stride;
        idx[u] = i;
        int ii = (i < total4) ? i : 0;          // clamp; masked at store
        int c4  = ii & (C4 - 1);
        int tmp = ii >> 6;                       // bt*10 + m
        int m   = tmp % 10;
        int bt  = tmp / 10;
        const float4* row = in + (long long)bt * IN_ROW4;
        pa[u] = row + c_n0[m] * C4 + c4;
        pb[u] = row + c_n1[m] * C4 + c4;
        int n2 = c_n2[m];
        pc[u] = (n2 >= 0) ? (row + n2 * C4 + c4) : nullptr;
        sc[u] = c_scale[m];
    }

    // Front-batch ALL loads: maximizes outstanding LDG.128 before any
    // store dependency can stall the warp.
    float4 a[UNROLL], b[UNROLL], c[UNROLL];
    #pragma unroll
    for (int u = 0; u < UNROLL; u++) a[u] = ld_cs4(pa[u]);
    #pragma unroll
    for (int u = 0; u < UNROLL; u++) b[u] = ld_cs4(pb[u]);
    #pragma unroll
    for (int u = 0; u < UNROLL; u++)
        if (pc[u]) c[u] = ld_cs4(pc[u]);

    #pragma unroll
    for (int u = 0; u < UNROLL; u++) {
        float sx = a[u].x + b[u].x;
        float sy = a[u].y + b[u].y;
        float sz = a[u].z + b[u].z;
        float sw = a[u].w + b[u].w;
        if (pc[u]) {
            sx += c[u].x; sy += c[u].y; sz += c[u].z; sw += c[u].w;
        }
        float s = sc[u];
        float4 r = make_float4(sx * s, sy * s, sz * s, sw * s);
        if (idx[u] < total4) st_cs4(out + idx[u], r);
    }
}

extern "C" void kernel_launch(void* const* d_in, const int* in_sizes, int n_in,
                              void* d_out, int out_size)
{
    const float4* in  = (const float4*)d_in[0];
    float4*       out = (float4*)d_out;

    int total4  = out_size / 4;
    int threads = 256;
    int per_blk = threads * UNROLL;
    int blocks  = (total4 + per_blk - 1) / per_blk;
    s_down_sampling_kernel<<<blocks, threads>>>(in, out, total4);
}